// round 7
// baseline (speedup 1.0000x reference)
#include <cuda_runtime.h>
#include <math.h>
#include <stdint.h>

#define Bdim 8
#define Vn   256
#define Hn   128
#define NR   2048      /* B*V   */
#define NE   524288    /* B*V*V */

// ---------------- device scratch (no allocation allowed) ----------------
__device__ float g_Uh[NR * Hn];
__device__ float g_Vh[NR * Hn];
__device__ float g_Ah[NR * Hn];
__device__ float g_Bh[NR * Hn];
__device__ float g_hnew[NR * Hn];
__device__ float g_esum[Hn];
__device__ float g_esq[Hn];
__device__ float g_escale[Hn];
__device__ float g_eshift[Hn];
__device__ float g_enew[(size_t)NE * Hn];   // 268 MB spill of e_new

// ---------------- helpers ----------------
__device__ __forceinline__ unsigned smem_u32(const void* p) {
    unsigned a;
    asm("{ .reg .u64 t; cvta.to.shared.u64 t, %1; cvt.u32.u64 %0, t; }"
        : "=r"(a) : "l"(p));
    return a;
}
__device__ __forceinline__ void cp_async16(unsigned dst, const void* src) {
    asm volatile("cp.async.cg.shared.global [%0], [%1], 16;\n" :: "r"(dst), "l"(src));
}
__device__ __forceinline__ uint32_t f2tf32(float f) {
    uint32_t u;
    asm("cvt.rna.tf32.f32 %0, %1;" : "=r"(u) : "f"(f));
    return u;
}
__device__ __forceinline__ float fast_sigmoid(float x) {
    float t;
    asm("tanh.approx.f32 %0, %1;" : "=f"(t) : "f"(0.5f * x));
    return 0.5f * t + 0.5f;
}

// ---------------- kernels ----------------

__global__ void k_zero() {
    int t = threadIdx.x;
    if (t < Hn) { g_esum[t] = 0.f; g_esq[t] = 0.f; }
}

// two h-linears per launch (keeps pass1 at profiled stream slot 4)
#define HL_STR 132
__global__ __launch_bounds__(256)
void k_hlin2(const float* __restrict__ h,
             const float* __restrict__ W1, const float* __restrict__ b1,
             const float* __restrict__ W2, const float* __restrict__ b2,
             int which) {
    __shared__ float hs[16 * HL_STR];
    __shared__ float Ws[128 * HL_STR];
    const int t = threadIdx.x;
    const int lane = t & 31, wq = t >> 5;
    const int rbase = blockIdx.x * 16;
    {
        int idx0 = t, idx1 = t + 256;
        int r0 = idx0 >> 5, kq0 = idx0 & 31;
        int r1 = idx1 >> 5, kq1 = idx1 & 31;
        *(float4*)(hs + r0 * HL_STR + kq0 * 4) = *(const float4*)(h + (size_t)(rbase + r0) * Hn + kq0 * 4);
        *(float4*)(hs + r1 * HL_STR + kq1 * 4) = *(const float4*)(h + (size_t)(rbase + r1) * Hn + kq1 * 4);
    }
    const float* Wp[2]; const float* bp[2]; float* Op[2];
    Wp[0] = W1; Wp[1] = W2; bp[0] = b1; bp[1] = b2;
    if (which) { Op[0] = g_Ah; Op[1] = g_Bh; } else { Op[0] = g_Uh; Op[1] = g_Vh; }
    const int r0 = wq * 2, r1 = wq * 2 + 1;
    for (int a = 0; a < 2; a++) {
        __syncthreads();
        const float* W = Wp[a];
#pragma unroll
        for (int i = 0; i < 16; i++) {
            int idx = t + i * 256;
            int o = idx >> 5, kq = idx & 31;
            *(float4*)(Ws + o * HL_STR + kq * 4) = *(const float4*)(W + (size_t)o * Hn + kq * 4);
        }
        __syncthreads();
        float acc0[4] = {0.f, 0.f, 0.f, 0.f};
        float acc1[4] = {0.f, 0.f, 0.f, 0.f};
#pragma unroll 4
        for (int k4 = 0; k4 < 32; k4++) {
            float4 h0 = *(const float4*)(hs + r0 * HL_STR + k4 * 4);
            float4 h1 = *(const float4*)(hs + r1 * HL_STR + k4 * 4);
#pragma unroll
            for (int c = 0; c < 4; c++) {
                float4 w = *(const float4*)(Ws + (lane + 32 * c) * HL_STR + k4 * 4);
                acc0[c] += h0.x * w.x + h0.y * w.y + h0.z * w.z + h0.w * w.w;
                acc1[c] += h1.x * w.x + h1.y * w.y + h1.z * w.z + h1.w * w.w;
            }
        }
        float* O = Op[a];
        const float* bb = bp[a];
#pragma unroll
        for (int c = 0; c < 4; c++) {
            int col = lane + 32 * c;
            float bv = bb[col];
            O[(size_t)(rbase + r0) * Hn + col] = acc0[c] + bv;
            O[(size_t)(rbase + r1) * Hn + col] = acc1[c] + bv;
        }
    }
}

// Pass 1: tf32 mma.sync GEMM + coalesced fused epilogue.
// One block per p=(b,i). 256 threads = 8 warps in a 4(j) x 2(h) grid,
// warp tile 64x64, full 256x128 panel in one shot, K=128 (16 ksteps of k8).
// LDS/MMA = 1.0 (vs 2.0 at 32x32 tiles). Epilogue: fragments transposed
// through the dead e-tile buffer; all global traffic 128B/warp coalesced.
#define WT_STRIDE 136
#define AS_STRIDE 132
#define AS_OFF    17408
#define GS_OFF    51200
#define SMEM_FLOATS 51512
// reduction scratch inside retired WtS area (floats):
#define RED_SQ    1056
#define RED_AGG   2112

__global__ __launch_bounds__(256, 1)
void k_pass1(const float* __restrict__ e,
             const int* __restrict__ graph,
             const float* __restrict__ Cw,
             const float* __restrict__ Cb) {
    extern __shared__ float sm[];
    uint32_t* WtS = (uint32_t*)sm;
    float* As   = sm + AS_OFF;            // 256 x AS_STRIDE
    int*   gs   = (int*)(sm + GS_OFF);    // 256 ints

    const int p = blockIdx.x;
    const int b = p >> 8;
    const int t = threadIdx.x;
    const int lane = t & 31;
    const int wid  = t >> 3 >> 2;          // t>>5
    const int wj = wid >> 1;               // 0..3 : j block of 64
    const int wh = wid & 1;                // 0..1 : h block of 64
    const int gid = lane >> 2;             // 0..7
    const int tig = lane & 3;              // 0..3

    for (int i = t; i < Hn * Hn; i += 256) {
        int n = i >> 7, k = i & 127;
        WtS[k * WT_STRIDE + n] = f2tf32(Cw[i]);
    }
    gs[t] = graph[p * Vn + t];

    // per-lane bias for 4 channels h = lane*4..lane*4+3
    const int h4 = lane * 4;
    float4 bias4;
    {
        float4 bb = *(const float4*)(g_Bh + (size_t)p * Hn + h4);
        float4 cb = *(const float4*)(Cb + h4);
        bias4 = make_float4(bb.x + cb.x, bb.y + cb.y, bb.z + cb.z, bb.w + cb.w);
    }

    // stage full e panel: 8192 float4, 32 per thread
    const float* ebase = e + (size_t)p * Vn * Hn;
    {
        unsigned dbase = smem_u32(As);
#pragma unroll
        for (int i = 0; i < 32; i++) {
            int fid = i * 256 + t;
            int row = fid >> 5, kq = fid & 31;
            cp_async16(dbase + (row * AS_STRIDE + kq * 4) * 4,
                       ebase + (size_t)row * Hn + kq * 4);
        }
        asm volatile("cp.async.commit_group;\n");
        asm volatile("cp.async.wait_group 0;\n");
    }
    __syncthreads();

    const uint32_t* AbufU = (const uint32_t*)As;

    // ---- GEMM: 64x64 per warp ----
    float cf[4][8][4];
#pragma unroll
    for (int rg = 0; rg < 4; rg++)
#pragma unroll
        for (int nt = 0; nt < 8; nt++)
#pragma unroll
            for (int q = 0; q < 4; q++) cf[rg][nt][q] = 0.f;

#pragma unroll 2
    for (int ks = 0; ks < 16; ks++) {
        int k0 = ks * 8 + tig;
        uint32_t a[4][4];
#pragma unroll
        for (int rg = 0; rg < 4; rg++) {
            int r = wj * 64 + rg * 16 + gid;
            a[rg][0] = AbufU[r * AS_STRIDE + k0];        // raw fp32 bits (HW->tf32)
            a[rg][1] = AbufU[(r + 8) * AS_STRIDE + k0];
            a[rg][2] = AbufU[r * AS_STRIDE + k0 + 4];
            a[rg][3] = AbufU[(r + 8) * AS_STRIDE + k0 + 4];
        }
        uint32_t bfr[8][2];
#pragma unroll
        for (int nt = 0; nt < 8; nt++) {
            int n = wh * 64 + nt * 8 + gid;
            bfr[nt][0] = WtS[k0 * WT_STRIDE + n];
            bfr[nt][1] = WtS[(k0 + 4) * WT_STRIDE + n];
        }
#pragma unroll
        for (int rg = 0; rg < 4; rg++)
#pragma unroll
            for (int nt = 0; nt < 8; nt++) {
                asm volatile(
                    "mma.sync.aligned.m16n8k8.row.col.f32.tf32.tf32.f32 "
                    "{%0,%1,%2,%3},{%4,%5,%6,%7},{%8,%9},{%0,%1,%2,%3};"
                    : "+f"(cf[rg][nt][0]), "+f"(cf[rg][nt][1]),
                      "+f"(cf[rg][nt][2]), "+f"(cf[rg][nt][3])
                    : "r"(a[rg][0]), "r"(a[rg][1]), "r"(a[rg][2]), "r"(a[rg][3]),
                      "r"(bfr[nt][0]), "r"(bfr[nt][1]));
            }
    }

    // ---- transpose fragments into the dead e-tile buffer ----
    __syncthreads();   // all warps done reading As
#pragma unroll
    for (int rg = 0; rg < 4; rg++)
#pragma unroll
        for (int half = 0; half < 2; half++) {
            int jl = wj * 64 + rg * 16 + half * 8 + gid;
#pragma unroll
            for (int nt = 0; nt < 8; nt++) {
                int h = wh * 64 + nt * 8 + tig * 2;
                *(float2*)(As + jl * AS_STRIDE + h) =
                    make_float2(cf[rg][nt][half * 2], cf[rg][nt][half * 2 + 1]);
            }
        }
    __syncthreads();

    // ---- coalesced epilogue: warp owns rows [wid*32, wid*32+32) ----
    float4 sum4 = make_float4(0.f, 0.f, 0.f, 0.f);
    float4 sq4  = make_float4(0.f, 0.f, 0.f, 0.f);
    float4 agg4 = make_float4(0.f, 0.f, 0.f, 0.f);
    const float* AhB = g_Ah + (size_t)b * Vn * Hn;
    const float* VhB = g_Vh + (size_t)b * Vn * Hn;
#pragma unroll 8
    for (int r = 0; r < 32; r++) {
        int j = wid * 32 + r;
        float4 cv = *(const float4*)(As + j * AS_STRIDE + h4);
        float4 ah = *(const float4*)(AhB + (size_t)j * Hn + h4);
        float4 en;
        en.x = cv.x + ah.x + bias4.x;
        en.y = cv.y + ah.y + bias4.y;
        en.z = cv.z + ah.z + bias4.z;
        en.w = cv.w + ah.w + bias4.w;
        *(float4*)(g_enew + ((size_t)p * Vn + j) * Hn + h4) = en;
        sum4.x += en.x; sum4.y += en.y; sum4.z += en.z; sum4.w += en.w;
        sq4.x += en.x * en.x; sq4.y += en.y * en.y;
        sq4.z += en.z * en.z; sq4.w += en.w * en.w;
        if (!gs[j]) {
            float4 vh = *(const float4*)(VhB + (size_t)j * Hn + h4);
            agg4.x += fast_sigmoid(en.x) * vh.x;
            agg4.y += fast_sigmoid(en.y) * vh.y;
            agg4.z += fast_sigmoid(en.z) * vh.z;
            agg4.w += fast_sigmoid(en.w) * vh.w;
        }
    }

    // ---- block reduction via retired WtS area ----
    float* redS = sm;
    __syncthreads();
    *(float4*)(redS + wid * AS_STRIDE + h4)           = sum4;
    *(float4*)(redS + RED_SQ + wid * AS_STRIDE + h4)  = sq4;
    *(float4*)(redS + RED_AGG + wid * AS_STRIDE + h4) = agg4;
    __syncthreads();
    if (t < Hn) {
        float s = 0.f, q = 0.f, g = 0.f;
#pragma unroll
        for (int w = 0; w < 8; w++) {
            s += redS[w * AS_STRIDE + t];
            q += redS[RED_SQ + w * AS_STRIDE + t];
            g += redS[RED_AGG + w * AS_STRIDE + t];
        }
        atomicAdd(&g_esum[t], s);
        atomicAdd(&g_esq[t],  q);
        g_hnew[(size_t)p * Hn + t] = g_Uh[(size_t)p * Hn + t] + g;
    }
}

// h-side batchnorm + residual relu. One block per channel.
__global__ void k_hbn(const float* __restrict__ hin,
                      const float* __restrict__ gam,
                      const float* __restrict__ bet,
                      float* __restrict__ out) {
    int h = blockIdx.x, t = threadIdx.x;
    float v[8];
    float s = 0.f, q = 0.f;
#pragma unroll
    for (int r = 0; r < 8; r++) {
        float x = g_hnew[(size_t)(t * 8 + r) * Hn + h];
        v[r] = x; s += x; q += x * x;
    }
    __shared__ float rs[256], rq[256];
    rs[t] = s; rq[t] = q; __syncthreads();
    for (int o = 128; o > 0; o >>= 1) {
        if (t < o) { rs[t] += rs[t + o]; rq[t] += rq[t + o]; }
        __syncthreads();
    }
    __shared__ float sc, sh;
    if (t == 0) {
        float mean = rs[0] * (1.0f / NR);
        float var  = rq[0] * (1.0f / NR) - mean * mean;
        float scale = gam[h] * rsqrtf(var + 1e-5f);
        sc = scale; sh = bet[h] - mean * scale;
    }
    __syncthreads();
#pragma unroll
    for (int r = 0; r < 8; r++) {
        int row = t * 8 + r;
        float y = fmaxf(v[r] * sc + sh, 0.f);
        out[(size_t)row * Hn + h] = hin[(size_t)row * Hn + h] + y;
    }
}

__global__ void k_estats(const float* __restrict__ gam,
                         const float* __restrict__ bet) {
    int t = threadIdx.x;
    if (t < Hn) {
        float mean = g_esum[t] * (1.0f / NE);
        float var  = g_esq[t] * (1.0f / NE) - mean * mean;
        float scale = gam[t] * rsqrtf(var + 1e-5f);
        g_escale[t] = scale;
        g_eshift[t] = bet[t] - mean * scale;
    }
}

// pass 2 over e: normalize + relu + residual, pure streaming float4
__global__ void k_epass2(const float* __restrict__ ein,
                         float* __restrict__ eout) {
    size_t idx = (size_t)blockIdx.x * blockDim.x + threadIdx.x;  // float4 idx
    int h0 = (int)((idx * 4) & 127);
    float4 x = ((const float4*)g_enew)[idx];
    float4 a = ((const float4*)ein)[idx];
    float4 o;
    o.x = a.x + fmaxf(x.x * g_escale[h0]     + g_eshift[h0],     0.f);
    o.y = a.y + fmaxf(x.y * g_escale[h0 + 1] + g_eshift[h0 + 1], 0.f);
    o.z = a.z + fmaxf(x.z * g_escale[h0 + 2] + g_eshift[h0 + 2], 0.f);
    o.w = a.w + fmaxf(x.w * g_escale[h0 + 3] + g_eshift[h0 + 3], 0.f);
    ((float4*)eout)[idx] = o;
}

// ---------------- launch ----------------
extern "C" void kernel_launch(void* const* d_in, const int* in_sizes, int n_in,
                              void* d_out, int out_size) {
    const float* h   = (const float*)d_in[0];
    const float* e   = (const float*)d_in[1];
    const int*   gra = (const int*)  d_in[2];
    const float* Uw  = (const float*)d_in[3],  *Ub = (const float*)d_in[4];
    const float* Vw  = (const float*)d_in[5],  *Vb = (const float*)d_in[6];
    const float* Aw  = (const float*)d_in[7],  *Ab = (const float*)d_in[8];
    const float* Bw  = (const float*)d_in[9],  *Bb = (const float*)d_in[10];
    const float* Cw  = (const float*)d_in[11], *Cb = (const float*)d_in[12];
    const float* gh  = (const float*)d_in[13], *bh = (const float*)d_in[14];
    const float* ge  = (const float*)d_in[15], *be = (const float*)d_in[16];

    float* out  = (float*)d_out;
    float* hout = out;                        // [2048,128]
    float* eout = out + (size_t)NR * Hn;      // [8,256,256,128]

    const int smemE = SMEM_FLOATS * 4;        // ~206 KB
    cudaFuncSetAttribute(k_pass1, cudaFuncAttributeMaxDynamicSharedMemorySize, smemE);

    k_zero  <<<1, 128>>>();
    k_hlin2 <<<128, 256>>>(h, Uw, Ub, Vw, Vb, 0);
    k_hlin2 <<<128, 256>>>(h, Aw, Ab, Bw, Bb, 1);
    k_pass1 <<<NR, 256, smemE>>>(e, gra, Cw, Cb);
    k_hbn   <<<Hn, 256>>>(h, gh, bh, hout);
    k_estats<<<1, 128>>>(ge, be);
    k_epass2<<<65536, 256>>>(e, eout);
}

// round 8
// speedup vs baseline: 1.2030x; 1.2030x over previous
#include <cuda_runtime.h>
#include <math.h>
#include <stdint.h>

#define Bdim 8
#define Vn   256
#define Hn   128
#define NR   2048      /* B*V   */
#define NE   524288    /* B*V*V */

// ---------------- device scratch (no allocation allowed) ----------------
__device__ float g_Uh[NR * Hn];
__device__ float g_Vh[NR * Hn];
__device__ float g_Ah[NR * Hn];
__device__ float g_Bh[NR * Hn];
__device__ float g_hnew[NR * Hn];
__device__ float g_esum[Hn];
__device__ float g_esq[Hn];
__device__ float g_escale[Hn];
__device__ float g_eshift[Hn];
__device__ float g_enew[(size_t)NE * Hn];   // 268 MB spill of e_new

// ---------------- helpers ----------------
__device__ __forceinline__ unsigned smem_u32(const void* p) {
    unsigned a;
    asm("{ .reg .u64 t; cvta.to.shared.u64 t, %1; cvt.u32.u64 %0, t; }"
        : "=r"(a) : "l"(p));
    return a;
}
__device__ __forceinline__ void cp_async16(unsigned dst, const void* src) {
    asm volatile("cp.async.cg.shared.global [%0], [%1], 16;\n" :: "r"(dst), "l"(src));
}
__device__ __forceinline__ uint32_t f2tf32(float f) {
    uint32_t u;
    asm("cvt.rna.tf32.f32 %0, %1;" : "=r"(u) : "f"(f));
    return u;
}
__device__ __forceinline__ float fast_sigmoid(float x) {
    float t;
    asm("tanh.approx.f32 %0, %1;" : "=f"(t) : "f"(0.5f * x));
    return 0.5f * t + 0.5f;
}

// ---------------- kernels ----------------

__global__ void k_zero() {
    int t = threadIdx.x;
    if (t < Hn) { g_esum[t] = 0.f; g_esq[t] = 0.f; }
}

// two h-linears per launch (keeps pass1 at profiled stream slot 4)
#define HL_STR 132
__global__ __launch_bounds__(256)
void k_hlin2(const float* __restrict__ h,
             const float* __restrict__ W1, const float* __restrict__ b1,
             const float* __restrict__ W2, const float* __restrict__ b2,
             int which) {
    __shared__ float hs[16 * HL_STR];
    __shared__ float Ws[128 * HL_STR];
    const int t = threadIdx.x;
    const int lane = t & 31, wq = t >> 5;
    const int rbase = blockIdx.x * 16;
    {
        int idx0 = t, idx1 = t + 256;
        int r0 = idx0 >> 5, kq0 = idx0 & 31;
        int r1 = idx1 >> 5, kq1 = idx1 & 31;
        *(float4*)(hs + r0 * HL_STR + kq0 * 4) = *(const float4*)(h + (size_t)(rbase + r0) * Hn + kq0 * 4);
        *(float4*)(hs + r1 * HL_STR + kq1 * 4) = *(const float4*)(h + (size_t)(rbase + r1) * Hn + kq1 * 4);
    }
    const float* Wp[2]; const float* bp[2]; float* Op[2];
    Wp[0] = W1; Wp[1] = W2; bp[0] = b1; bp[1] = b2;
    if (which) { Op[0] = g_Ah; Op[1] = g_Bh; } else { Op[0] = g_Uh; Op[1] = g_Vh; }
    const int r0 = wq * 2, r1 = wq * 2 + 1;
    for (int a = 0; a < 2; a++) {
        __syncthreads();
        const float* W = Wp[a];
#pragma unroll
        for (int i = 0; i < 16; i++) {
            int idx = t + i * 256;
            int o = idx >> 5, kq = idx & 31;
            *(float4*)(Ws + o * HL_STR + kq * 4) = *(const float4*)(W + (size_t)o * Hn + kq * 4);
        }
        __syncthreads();
        float acc0[4] = {0.f, 0.f, 0.f, 0.f};
        float acc1[4] = {0.f, 0.f, 0.f, 0.f};
#pragma unroll 4
        for (int k4 = 0; k4 < 32; k4++) {
            float4 h0 = *(const float4*)(hs + r0 * HL_STR + k4 * 4);
            float4 h1 = *(const float4*)(hs + r1 * HL_STR + k4 * 4);
#pragma unroll
            for (int c = 0; c < 4; c++) {
                float4 w = *(const float4*)(Ws + (lane + 32 * c) * HL_STR + k4 * 4);
                acc0[c] += h0.x * w.x + h0.y * w.y + h0.z * w.z + h0.w * w.w;
                acc1[c] += h1.x * w.x + h1.y * w.y + h1.z * w.z + h1.w * w.w;
            }
        }
        float* O = Op[a];
        const float* bb = bp[a];
#pragma unroll
        for (int c = 0; c < 4; c++) {
            int col = lane + 32 * c;
            float bv = bb[col];
            O[(size_t)(rbase + r0) * Hn + col] = acc0[c] + bv;
            O[(size_t)(rbase + r1) * Hn + col] = acc1[c] + bv;
        }
    }
}

// Pass 1: tf32 mma.sync GEMM + coalesced fused epilogue.
// One block per p=(b,i). 512 threads = 16 warps (4x4), warp tile 32x32,
// j in 2 chunks of 128 rows, K=128 (16 ksteps of k8).
// W tile stored XOR-swizzled: WtS[k*128 + (n ^ ((k&3)<<3))] -> B-fragment
// LDS conflict-free (was 8-way). A tile stride 132 (conflict-free).
// Epilogue transposes fragments through the dead e-tile buffer; all global
// traffic 128B/warp coalesced.
#define AS_STRIDE 132
#define AS_OFF    16384
#define AS_BUF    16896
#define GS_OFF    50176
#define SMEM_FLOATS 50432
// reduction scratch inside retired WtS area (floats):
#define RED_SQ    2112
#define RED_AGG   4224

__global__ __launch_bounds__(512, 1)
void k_pass1(const float* __restrict__ e,
             const int* __restrict__ graph,
             const float* __restrict__ Cw,
             const float* __restrict__ Cb) {
    extern __shared__ float sm[];
    uint32_t* WtS = (uint32_t*)sm;        // 128 x 128, xor-swizzled
    float* As   = sm + AS_OFF;
    int*   gs   = (int*)(sm + GS_OFF);    // 256 ints

    const int p = blockIdx.x;
    const int b = p >> 8;
    const int t = threadIdx.x;
    const int lane = t & 31;
    const int wid  = t >> 5;
    const int wr = wid >> 2, wc = wid & 3;
    const int gid = lane >> 2, tig = lane & 3;

    for (int i = t; i < Hn * Hn; i += 512) {
        int n = i >> 7, k = i & 127;
        WtS[k * 128 + (n ^ ((k & 3) << 3))] = f2tf32(Cw[i]);
    }
    if (t < 256) gs[t] = graph[p * Vn + t];

    // per-lane bias for 4 channels h = lane*4..lane*4+3
    const int h4 = lane * 4;
    float4 bias4;
    {
        float4 bb = *(const float4*)(g_Bh + (size_t)p * Hn + h4);
        float4 cb = *(const float4*)(Cb + h4);
        bias4 = make_float4(bb.x + cb.x, bb.y + cb.y, bb.z + cb.z, bb.w + cb.w);
    }

    float4 sum4 = make_float4(0.f, 0.f, 0.f, 0.f);
    float4 sq4  = make_float4(0.f, 0.f, 0.f, 0.f);
    float4 agg4 = make_float4(0.f, 0.f, 0.f, 0.f);

    const float* ebase = e + (size_t)p * Vn * Hn;
    {
        unsigned dbase = smem_u32(As);
#pragma unroll
        for (int i = 0; i < 8; i++) {
            int fid = i * 512 + t;
            int row = fid >> 5, kq = fid & 31;
            cp_async16(dbase + (row * AS_STRIDE + kq * 4) * 4,
                       ebase + (size_t)row * Hn + kq * 4);
        }
        asm volatile("cp.async.commit_group;\n");
    }

    for (int c = 0; c < 2; c++) {
        if (c == 0) {
            unsigned dbase = smem_u32(As + AS_BUF);
#pragma unroll
            for (int i = 0; i < 8; i++) {
                int fid = i * 512 + t;
                int row = fid >> 5, kq = fid & 31;
                cp_async16(dbase + (row * AS_STRIDE + kq * 4) * 4,
                           ebase + (size_t)(128 + row) * Hn + kq * 4);
            }
            asm volatile("cp.async.commit_group;\n");
            asm volatile("cp.async.wait_group 1;\n");
        } else {
            asm volatile("cp.async.wait_group 0;\n");
        }
        __syncthreads();

        float* Abuf = As + c * AS_BUF;
        const uint32_t* AbufU = (const uint32_t*)Abuf;
        const int jb = c * 128;

        float cf[2][4][4];
#pragma unroll
        for (int rg = 0; rg < 2; rg++)
#pragma unroll
            for (int nt = 0; nt < 4; nt++)
#pragma unroll
                for (int q = 0; q < 4; q++) cf[rg][nt][q] = 0.f;

        const uint32_t xr = (uint32_t)(tig << 3);   // lane-constant W swizzle
#pragma unroll 2
        for (int ks = 0; ks < 16; ks++) {
            int k0 = ks * 8 + tig;
            uint32_t a[2][4];
#pragma unroll
            for (int rg = 0; rg < 2; rg++) {
                int r = wr * 32 + rg * 16 + gid;
                a[rg][0] = AbufU[r * AS_STRIDE + k0];        // raw fp32 bits (HW->tf32)
                a[rg][1] = AbufU[(r + 8) * AS_STRIDE + k0];
                a[rg][2] = AbufU[r * AS_STRIDE + k0 + 4];
                a[rg][3] = AbufU[(r + 8) * AS_STRIDE + k0 + 4];
            }
            uint32_t bfr[4][2];
#pragma unroll
            for (int nt = 0; nt < 4; nt++) {
                int n = wc * 32 + nt * 8 + gid;
                bfr[nt][0] = WtS[k0 * 128 + (n ^ xr)];
                bfr[nt][1] = WtS[(k0 + 4) * 128 + (n ^ xr)];
            }
#pragma unroll
            for (int rg = 0; rg < 2; rg++)
#pragma unroll
                for (int nt = 0; nt < 4; nt++) {
                    asm volatile(
                        "mma.sync.aligned.m16n8k8.row.col.f32.tf32.tf32.f32 "
                        "{%0,%1,%2,%3},{%4,%5,%6,%7},{%8,%9},{%0,%1,%2,%3};"
                        : "+f"(cf[rg][nt][0]), "+f"(cf[rg][nt][1]),
                          "+f"(cf[rg][nt][2]), "+f"(cf[rg][nt][3])
                        : "r"(a[rg][0]), "r"(a[rg][1]), "r"(a[rg][2]), "r"(a[rg][3]),
                          "r"(bfr[nt][0]), "r"(bfr[nt][1]));
                }
        }

        // ---- transpose fragments into the dead e-tile buffer ----
        __syncthreads();   // all warps done reading Abuf
#pragma unroll
        for (int rg = 0; rg < 2; rg++)
#pragma unroll
            for (int half = 0; half < 2; half++) {
                int jl = wr * 32 + rg * 16 + half * 8 + gid;
#pragma unroll
                for (int nt = 0; nt < 4; nt++) {
                    int h = wc * 32 + nt * 8 + tig * 2;
                    *(float2*)(Abuf + jl * AS_STRIDE + h) =
                        make_float2(cf[rg][nt][half * 2], cf[rg][nt][half * 2 + 1]);
                }
            }
        __syncthreads();

        // ---- coalesced epilogue: warp owns rows [wid*8, wid*8+8) ----
        const float* AhB = g_Ah + (size_t)b * Vn * Hn;
        const float* VhB = g_Vh + (size_t)b * Vn * Hn;
#pragma unroll
        for (int r = 0; r < 8; r++) {
            int jl = wid * 8 + r;
            int j  = jb + jl;
            float4 cv = *(const float4*)(Abuf + jl * AS_STRIDE + h4);
            float4 ah = *(const float4*)(AhB + (size_t)j * Hn + h4);
            float4 en;
            en.x = cv.x + ah.x + bias4.x;
            en.y = cv.y + ah.y + bias4.y;
            en.z = cv.z + ah.z + bias4.z;
            en.w = cv.w + ah.w + bias4.w;
            *(float4*)(g_enew + ((size_t)p * Vn + j) * Hn + h4) = en;
            sum4.x += en.x; sum4.y += en.y; sum4.z += en.z; sum4.w += en.w;
            sq4.x += en.x * en.x; sq4.y += en.y * en.y;
            sq4.z += en.z * en.z; sq4.w += en.w * en.w;
            if (!gs[j]) {
                float4 vh = *(const float4*)(VhB + (size_t)j * Hn + h4);
                agg4.x += fast_sigmoid(en.x) * vh.x;
                agg4.y += fast_sigmoid(en.y) * vh.y;
                agg4.z += fast_sigmoid(en.z) * vh.z;
                agg4.w += fast_sigmoid(en.w) * vh.w;
            }
        }
        __syncthreads();
    }

    // ---- block reduction via retired WtS area ----
    float* redS = sm;
    *(float4*)(redS + wid * AS_STRIDE + h4)           = sum4;
    *(float4*)(redS + RED_SQ + wid * AS_STRIDE + h4)  = sq4;
    *(float4*)(redS + RED_AGG + wid * AS_STRIDE + h4) = agg4;
    __syncthreads();
    if (t < Hn) {
        float s = 0.f, q = 0.f, g = 0.f;
#pragma unroll
        for (int w = 0; w < 16; w++) {
            s += redS[w * AS_STRIDE + t];
            q += redS[RED_SQ + w * AS_STRIDE + t];
            g += redS[RED_AGG + w * AS_STRIDE + t];
        }
        atomicAdd(&g_esum[t], s);
        atomicAdd(&g_esq[t],  q);
        g_hnew[(size_t)p * Hn + t] = g_Uh[(size_t)p * Hn + t] + g;
    }
}

// h-side batchnorm + residual relu. One block per channel.
__global__ void k_hbn(const float* __restrict__ hin,
                      const float* __restrict__ gam,
                      const float* __restrict__ bet,
                      float* __restrict__ out) {
    int h = blockIdx.x, t = threadIdx.x;
    float v[8];
    float s = 0.f, q = 0.f;
#pragma unroll
    for (int r = 0; r < 8; r++) {
        float x = g_hnew[(size_t)(t * 8 + r) * Hn + h];
        v[r] = x; s += x; q += x * x;
    }
    __shared__ float rs[256], rq[256];
    rs[t] = s; rq[t] = q; __syncthreads();
    for (int o = 128; o > 0; o >>= 1) {
        if (t < o) { rs[t] += rs[t + o]; rq[t] += rq[t + o]; }
        __syncthreads();
    }
    __shared__ float sc, sh;
    if (t == 0) {
        float mean = rs[0] * (1.0f / NR);
        float var  = rq[0] * (1.0f / NR) - mean * mean;
        float scale = gam[h] * rsqrtf(var + 1e-5f);
        sc = scale; sh = bet[h] - mean * scale;
    }
    __syncthreads();
#pragma unroll
    for (int r = 0; r < 8; r++) {
        int row = t * 8 + r;
        float y = fmaxf(v[r] * sc + sh, 0.f);
        out[(size_t)row * Hn + h] = hin[(size_t)row * Hn + h] + y;
    }
}

__global__ void k_estats(const float* __restrict__ gam,
                         const float* __restrict__ bet) {
    int t = threadIdx.x;
    if (t < Hn) {
        float mean = g_esum[t] * (1.0f / NE);
        float var  = g_esq[t] * (1.0f / NE) - mean * mean;
        float scale = gam[t] * rsqrtf(var + 1e-5f);
        g_escale[t] = scale;
        g_eshift[t] = bet[t] - mean * scale;
    }
}

// pass 2 over e: normalize + relu + residual, pure streaming float4
__global__ void k_epass2(const float* __restrict__ ein,
                         float* __restrict__ eout) {
    size_t idx = (size_t)blockIdx.x * blockDim.x + threadIdx.x;  // float4 idx
    int h0 = (int)((idx * 4) & 127);
    float4 x = ((const float4*)g_enew)[idx];
    float4 a = ((const float4*)ein)[idx];
    float4 o;
    o.x = a.x + fmaxf(x.x * g_escale[h0]     + g_eshift[h0],     0.f);
    o.y = a.y + fmaxf(x.y * g_escale[h0 + 1] + g_eshift[h0 + 1], 0.f);
    o.z = a.z + fmaxf(x.z * g_escale[h0 + 2] + g_eshift[h0 + 2], 0.f);
    o.w = a.w + fmaxf(x.w * g_escale[h0 + 3] + g_eshift[h0 + 3], 0.f);
    ((float4*)eout)[idx] = o;
}

// ---------------- launch ----------------
extern "C" void kernel_launch(void* const* d_in, const int* in_sizes, int n_in,
                              void* d_out, int out_size) {
    const float* h   = (const float*)d_in[0];
    const float* e   = (const float*)d_in[1];
    const int*   gra = (const int*)  d_in[2];
    const float* Uw  = (const float*)d_in[3],  *Ub = (const float*)d_in[4];
    const float* Vw  = (const float*)d_in[5],  *Vb = (const float*)d_in[6];
    const float* Aw  = (const float*)d_in[7],  *Ab = (const float*)d_in[8];
    const float* Bw  = (const float*)d_in[9],  *Bb = (const float*)d_in[10];
    const float* Cw  = (const float*)d_in[11], *Cb = (const float*)d_in[12];
    const float* gh  = (const float*)d_in[13], *bh = (const float*)d_in[14];
    const float* ge  = (const float*)d_in[15], *be = (const float*)d_in[16];

    float* out  = (float*)d_out;
    float* hout = out;                        // [2048,128]
    float* eout = out + (size_t)NR * Hn;      // [8,256,256,128]

    const int smemE = SMEM_FLOATS * 4;        // ~202 KB
    cudaFuncSetAttribute(k_pass1, cudaFuncAttributeMaxDynamicSharedMemorySize, smemE);

    k_zero  <<<1, 128>>>();
    k_hlin2 <<<128, 256>>>(h, Uw, Ub, Vw, Vb, 0);
    k_hlin2 <<<128, 256>>>(h, Aw, Ab, Bw, Bb, 1);
    k_pass1 <<<NR, 512, smemE>>>(e, gra, Cw, Cb);
    k_hbn   <<<Hn, 256>>>(h, gh, bh, hout);
    k_estats<<<1, 128>>>(ge, be);
    k_epass2<<<65536, 256>>>(e, eout);
}

// round 9
// speedup vs baseline: 1.3097x; 1.0887x over previous
#include <cuda_runtime.h>
#include <math.h>
#include <stdint.h>

#define Bdim 8
#define Vn   256
#define Hn   128
#define NR   2048      /* B*V   */
#define NE   524288    /* B*V*V */

// ---------------- device scratch (no allocation allowed) ----------------
__device__ float g_Uh[NR * Hn];
__device__ float g_Vh[NR * Hn];
__device__ float g_Ah[NR * Hn];
__device__ float g_Bh[NR * Hn];
__device__ float g_hnew[NR * Hn];
__device__ float g_esum[Hn];
__device__ float g_esq[Hn];
__device__ float g_escale[Hn];
__device__ float g_eshift[Hn];
__device__ float g_enew[(size_t)NE * Hn];   // 268 MB spill of e_new

// ---------------- helpers ----------------
__device__ __forceinline__ unsigned smem_u32(const void* p) {
    unsigned a;
    asm("{ .reg .u64 t; cvta.to.shared.u64 t, %1; cvt.u32.u64 %0, t; }"
        : "=r"(a) : "l"(p));
    return a;
}
__device__ __forceinline__ void cp_async16(unsigned dst, const void* src) {
    asm volatile("cp.async.cg.shared.global [%0], [%1], 16;\n" :: "r"(dst), "l"(src));
}
__device__ __forceinline__ uint32_t f2tf32(float f) {
    uint32_t u;
    asm("cvt.rna.tf32.f32 %0, %1;" : "=r"(u) : "f"(f));
    return u;
}
__device__ __forceinline__ float fast_sigmoid(float x) {
    float t;
    asm("tanh.approx.f32 %0, %1;" : "=f"(t) : "f"(0.5f * x));
    return 0.5f * t + 0.5f;
}

// ---------------- kernels ----------------

__global__ void k_zero() {
    int t = threadIdx.x;
    if (t < Hn) { g_esum[t] = 0.f; g_esq[t] = 0.f; }
}

// two h-linears per launch (keeps pass1 at profiled stream slot 4)
#define HL_STR 132
__global__ __launch_bounds__(256)
void k_hlin2(const float* __restrict__ h,
             const float* __restrict__ W1, const float* __restrict__ b1,
             const float* __restrict__ W2, const float* __restrict__ b2,
             int which) {
    __shared__ float hs[16 * HL_STR];
    __shared__ float Ws[128 * HL_STR];
    const int t = threadIdx.x;
    const int lane = t & 31, wq = t >> 5;
    const int rbase = blockIdx.x * 16;
    {
        int idx0 = t, idx1 = t + 256;
        int r0 = idx0 >> 5, kq0 = idx0 & 31;
        int r1 = idx1 >> 5, kq1 = idx1 & 31;
        *(float4*)(hs + r0 * HL_STR + kq0 * 4) = *(const float4*)(h + (size_t)(rbase + r0) * Hn + kq0 * 4);
        *(float4*)(hs + r1 * HL_STR + kq1 * 4) = *(const float4*)(h + (size_t)(rbase + r1) * Hn + kq1 * 4);
    }
    const float* Wp[2]; const float* bp[2]; float* Op[2];
    Wp[0] = W1; Wp[1] = W2; bp[0] = b1; bp[1] = b2;
    if (which) { Op[0] = g_Ah; Op[1] = g_Bh; } else { Op[0] = g_Uh; Op[1] = g_Vh; }
    const int r0 = wq * 2, r1 = wq * 2 + 1;
    for (int a = 0; a < 2; a++) {
        __syncthreads();
        const float* W = Wp[a];
#pragma unroll
        for (int i = 0; i < 16; i++) {
            int idx = t + i * 256;
            int o = idx >> 5, kq = idx & 31;
            *(float4*)(Ws + o * HL_STR + kq * 4) = *(const float4*)(W + (size_t)o * Hn + kq * 4);
        }
        __syncthreads();
        float acc0[4] = {0.f, 0.f, 0.f, 0.f};
        float acc1[4] = {0.f, 0.f, 0.f, 0.f};
#pragma unroll 4
        for (int k4 = 0; k4 < 32; k4++) {
            float4 h0 = *(const float4*)(hs + r0 * HL_STR + k4 * 4);
            float4 h1 = *(const float4*)(hs + r1 * HL_STR + k4 * 4);
#pragma unroll
            for (int c = 0; c < 4; c++) {
                float4 w = *(const float4*)(Ws + (lane + 32 * c) * HL_STR + k4 * 4);
                acc0[c] += h0.x * w.x + h0.y * w.y + h0.z * w.z + h0.w * w.w;
                acc1[c] += h1.x * w.x + h1.y * w.y + h1.z * w.z + h1.w * w.w;
            }
        }
        float* O = Op[a];
        const float* bb = bp[a];
#pragma unroll
        for (int c = 0; c < 4; c++) {
            int col = lane + 32 * c;
            float bv = bb[col];
            O[(size_t)(rbase + r0) * Hn + col] = acc0[c] + bv;
            O[(size_t)(rbase + r1) * Hn + col] = acc1[c] + bv;
        }
    }
}

// Pass 1: tf32 mma.sync GEMM + coalesced fused epilogue, 2 CTAs/SM.
// One block per p=(b,i). 256 threads = 8 warps (2j x 4h), warp tile 32x32,
// j in 4 chunks of 64 rows (single-buffered; co-resident CTA hides staging),
// K=128 (16 ksteps of k8). smem ~104 KB -> 2 CTAs/SM.
#define WT_STRIDE 136
#define AS_STRIDE 132
#define AS_OFF    17408               /* floats */
#define GS_OFF    25856               /* floats: 17408 + 64*132 */
#define SMEM_FLOATS 26144
// reduction scratch inside retired WtS area (floats): 8 warps x 132
#define RED_SQ    1056
#define RED_AGG   2112

__global__ __launch_bounds__(256, 2)
void k_pass1(const float* __restrict__ e,
             const int* __restrict__ graph,
             const float* __restrict__ Cw,
             const float* __restrict__ Cb) {
    extern __shared__ float sm[];
    uint32_t* WtS = (uint32_t*)sm;        // 128 x WT_STRIDE
    float* As   = sm + AS_OFF;            // 64 x AS_STRIDE
    int*   gs   = (int*)(sm + GS_OFF);    // 256 ints

    const int p = blockIdx.x;
    const int b = p >> 8;
    const int t = threadIdx.x;
    const int lane = t & 31;
    const int wid  = t >> 5;
    const int wj = wid >> 2;              // 0..1 : j sub-tile of 32 in 64-chunk
    const int wh = wid & 3;               // 0..3 : h sub-tile of 32
    const int gid = lane >> 2;            // 0..7
    const int tig = lane & 3;             // 0..3

    // ---- stage W transposed, conflict-free STS ----
    // per warp-iteration: 4(k) x 8(n) blocklet; STS bank = 8*tig + gid + const
    {
        const int w8 = wid;               // 0..7
#pragma unroll
        for (int it = 0; it < 64; it++) {
            int bb = it * 8 + w8;         // blocklet 0..511
            int kb = bb & 31, nb = bb >> 5;
            int k = kb * 4 + tig;
            int n = nb * 8 + gid;
            WtS[k * WT_STRIDE + n] = f2tf32(Cw[(size_t)n * Hn + k]);
        }
    }
    gs[t] = graph[p * Vn + t];

    // per-lane bias for 4 channels h = lane*4..lane*4+3
    const int h4 = lane * 4;
    float4 bias4;
    {
        float4 bb = *(const float4*)(g_Bh + (size_t)p * Hn + h4);
        float4 cb = *(const float4*)(Cb + h4);
        bias4 = make_float4(bb.x + cb.x, bb.y + cb.y, bb.z + cb.z, bb.w + cb.w);
    }

    float4 sum4 = make_float4(0.f, 0.f, 0.f, 0.f);
    float4 sq4  = make_float4(0.f, 0.f, 0.f, 0.f);
    float4 agg4 = make_float4(0.f, 0.f, 0.f, 0.f);

    const float* ebase = e + (size_t)p * Vn * Hn;
    const float* AhB = g_Ah + (size_t)b * Vn * Hn;
    const float* VhB = g_Vh + (size_t)b * Vn * Hn;
    const unsigned dbase = smem_u32(As);
    const uint32_t* AbufU = (const uint32_t*)As;

    for (int jc = 0; jc < 4; jc++) {
        // ---- stage 64-row e chunk (2048 float4, 8 per thread) ----
#pragma unroll
        for (int i = 0; i < 8; i++) {
            int fid = i * 256 + t;
            int row = fid >> 5, kq = fid & 31;
            cp_async16(dbase + (row * AS_STRIDE + kq * 4) * 4,
                       ebase + (size_t)(jc * 64 + row) * Hn + kq * 4);
        }
        asm volatile("cp.async.commit_group;\n");
        asm volatile("cp.async.wait_group 0;\n");
        __syncthreads();

        // ---- GEMM: warp tile 32(j) x 32(h) ----
        float cf[2][4][4];
#pragma unroll
        for (int rg = 0; rg < 2; rg++)
#pragma unroll
            for (int nt = 0; nt < 4; nt++)
#pragma unroll
                for (int q = 0; q < 4; q++) cf[rg][nt][q] = 0.f;

#pragma unroll 2
        for (int ks = 0; ks < 16; ks++) {
            int k0 = ks * 8 + tig;
            uint32_t a[2][4];
#pragma unroll
            for (int rg = 0; rg < 2; rg++) {
                int r = wj * 32 + rg * 16 + gid;
                a[rg][0] = AbufU[r * AS_STRIDE + k0];        // raw fp32 bits (HW->tf32)
                a[rg][1] = AbufU[(r + 8) * AS_STRIDE + k0];
                a[rg][2] = AbufU[r * AS_STRIDE + k0 + 4];
                a[rg][3] = AbufU[(r + 8) * AS_STRIDE + k0 + 4];
            }
            uint32_t bfr[4][2];
#pragma unroll
            for (int nt = 0; nt < 4; nt++) {
                int n = wh * 32 + nt * 8 + gid;
                bfr[nt][0] = WtS[k0 * WT_STRIDE + n];
                bfr[nt][1] = WtS[(k0 + 4) * WT_STRIDE + n];
            }
#pragma unroll
            for (int rg = 0; rg < 2; rg++)
#pragma unroll
                for (int nt = 0; nt < 4; nt++) {
                    asm volatile(
                        "mma.sync.aligned.m16n8k8.row.col.f32.tf32.tf32.f32 "
                        "{%0,%1,%2,%3},{%4,%5,%6,%7},{%8,%9},{%0,%1,%2,%3};"
                        : "+f"(cf[rg][nt][0]), "+f"(cf[rg][nt][1]),
                          "+f"(cf[rg][nt][2]), "+f"(cf[rg][nt][3])
                        : "r"(a[rg][0]), "r"(a[rg][1]), "r"(a[rg][2]), "r"(a[rg][3]),
                          "r"(bfr[nt][0]), "r"(bfr[nt][1]));
                }
        }

        // ---- transpose fragments into the dead e-chunk buffer ----
        __syncthreads();
#pragma unroll
        for (int rg = 0; rg < 2; rg++)
#pragma unroll
            for (int half = 0; half < 2; half++) {
                int jl = wj * 32 + rg * 16 + half * 8 + gid;
#pragma unroll
                for (int nt = 0; nt < 4; nt++) {
                    int h = wh * 32 + nt * 8 + tig * 2;
                    *(float2*)(As + jl * AS_STRIDE + h) =
                        make_float2(cf[rg][nt][half * 2], cf[rg][nt][half * 2 + 1]);
                }
            }
        __syncthreads();

        // ---- coalesced epilogue: warp owns rows [wid*8, wid*8+8) of chunk ----
#pragma unroll
        for (int r = 0; r < 8; r++) {
            int jl = wid * 8 + r;
            int j  = jc * 64 + jl;
            float4 cv = *(const float4*)(As + jl * AS_STRIDE + h4);
            float4 ah = *(const float4*)(AhB + (size_t)j * Hn + h4);
            float4 en;
            en.x = cv.x + ah.x + bias4.x;
            en.y = cv.y + ah.y + bias4.y;
            en.z = cv.z + ah.z + bias4.z;
            en.w = cv.w + ah.w + bias4.w;
            *(float4*)(g_enew + ((size_t)p * Vn + j) * Hn + h4) = en;
            sum4.x += en.x; sum4.y += en.y; sum4.z += en.z; sum4.w += en.w;
            sq4.x += en.x * en.x; sq4.y += en.y * en.y;
            sq4.z += en.z * en.z; sq4.w += en.w * en.w;
            if (!gs[j]) {
                float4 vh = *(const float4*)(VhB + (size_t)j * Hn + h4);
                agg4.x += fast_sigmoid(en.x) * vh.x;
                agg4.y += fast_sigmoid(en.y) * vh.y;
                agg4.z += fast_sigmoid(en.z) * vh.z;
                agg4.w += fast_sigmoid(en.w) * vh.w;
            }
        }
        __syncthreads();
    }

    // ---- block reduction via retired WtS area ----
    float* redS = sm;
    *(float4*)(redS + wid * AS_STRIDE + h4)           = sum4;
    *(float4*)(redS + RED_SQ + wid * AS_STRIDE + h4)  = sq4;
    *(float4*)(redS + RED_AGG + wid * AS_STRIDE + h4) = agg4;
    __syncthreads();
    if (t < Hn) {
        float s = 0.f, q = 0.f, g = 0.f;
#pragma unroll
        for (int w = 0; w < 8; w++) {
            s += redS[w * AS_STRIDE + t];
            q += redS[RED_SQ + w * AS_STRIDE + t];
            g += redS[RED_AGG + w * AS_STRIDE + t];
        }
        atomicAdd(&g_esum[t], s);
        atomicAdd(&g_esq[t],  q);
        g_hnew[(size_t)p * Hn + t] = g_Uh[(size_t)p * Hn + t] + g;
    }
}

// h-side batchnorm + residual relu. One block per channel.
__global__ void k_hbn(const float* __restrict__ hin,
                      const float* __restrict__ gam,
                      const float* __restrict__ bet,
                      float* __restrict__ out) {
    int h = blockIdx.x, t = threadIdx.x;
    float v[8];
    float s = 0.f, q = 0.f;
#pragma unroll
    for (int r = 0; r < 8; r++) {
        float x = g_hnew[(size_t)(t * 8 + r) * Hn + h];
        v[r] = x; s += x; q += x * x;
    }
    __shared__ float rs[256], rq[256];
    rs[t] = s; rq[t] = q; __syncthreads();
    for (int o = 128; o > 0; o >>= 1) {
        if (t < o) { rs[t] += rs[t + o]; rq[t] += rq[t + o]; }
        __syncthreads();
    }
    __shared__ float sc, sh;
    if (t == 0) {
        float mean = rs[0] * (1.0f / NR);
        float var  = rq[0] * (1.0f / NR) - mean * mean;
        float scale = gam[h] * rsqrtf(var + 1e-5f);
        sc = scale; sh = bet[h] - mean * scale;
    }
    __syncthreads();
#pragma unroll
    for (int r = 0; r < 8; r++) {
        int row = t * 8 + r;
        float y = fmaxf(v[r] * sc + sh, 0.f);
        out[(size_t)row * Hn + h] = hin[(size_t)row * Hn + h] + y;
    }
}

__global__ void k_estats(const float* __restrict__ gam,
                         const float* __restrict__ bet) {
    int t = threadIdx.x;
    if (t < Hn) {
        float mean = g_esum[t] * (1.0f / NE);
        float var  = g_esq[t] * (1.0f / NE) - mean * mean;
        float scale = gam[t] * rsqrtf(var + 1e-5f);
        g_escale[t] = scale;
        g_eshift[t] = bet[t] - mean * scale;
    }
}

// pass 2 over e: normalize + relu + residual, pure streaming float4
__global__ void k_epass2(const float* __restrict__ ein,
                         float* __restrict__ eout) {
    size_t idx = (size_t)blockIdx.x * blockDim.x + threadIdx.x;  // float4 idx
    int h0 = (int)((idx * 4) & 127);
    float4 x = ((const float4*)g_enew)[idx];
    float4 a = ((const float4*)ein)[idx];
    float4 o;
    o.x = a.x + fmaxf(x.x * g_escale[h0]     + g_eshift[h0],     0.f);
    o.y = a.y + fmaxf(x.y * g_escale[h0 + 1] + g_eshift[h0 + 1], 0.f);
    o.z = a.z + fmaxf(x.z * g_escale[h0 + 2] + g_eshift[h0 + 2], 0.f);
    o.w = a.w + fmaxf(x.w * g_escale[h0 + 3] + g_eshift[h0 + 3], 0.f);
    ((float4*)eout)[idx] = o;
}

// ---------------- launch ----------------
extern "C" void kernel_launch(void* const* d_in, const int* in_sizes, int n_in,
                              void* d_out, int out_size) {
    const float* h   = (const float*)d_in[0];
    const float* e   = (const float*)d_in[1];
    const int*   gra = (const int*)  d_in[2];
    const float* Uw  = (const float*)d_in[3],  *Ub = (const float*)d_in[4];
    const float* Vw  = (const float*)d_in[5],  *Vb = (const float*)d_in[6];
    const float* Aw  = (const float*)d_in[7],  *Ab = (const float*)d_in[8];
    const float* Bw  = (const float*)d_in[9],  *Bb = (const float*)d_in[10];
    const float* Cw  = (const float*)d_in[11], *Cb = (const float*)d_in[12];
    const float* gh  = (const float*)d_in[13], *bh = (const float*)d_in[14];
    const float* ge  = (const float*)d_in[15], *be = (const float*)d_in[16];

    float* out  = (float*)d_out;
    float* hout = out;                        // [2048,128]
    float* eout = out + (size_t)NR * Hn;      // [8,256,256,128]

    const int smemE = SMEM_FLOATS * 4;        // 104576 B -> 2 CTAs/SM
    cudaFuncSetAttribute(k_pass1, cudaFuncAttributeMaxDynamicSharedMemorySize, smemE);

    k_zero  <<<1, 128>>>();
    k_hlin2 <<<128, 256>>>(h, Uw, Ub, Vw, Vb, 0);
    k_hlin2 <<<128, 256>>>(h, Aw, Ab, Bw, Bb, 1);
    k_pass1 <<<NR, 256, smemE>>>(e, gra, Cw, Cb);
    k_hbn   <<<Hn, 256>>>(h, gh, bh, hout);
    k_estats<<<1, 128>>>(ge, be);
    k_epass2<<<65536, 256>>>(e, eout);
}

// round 10
// speedup vs baseline: 1.3205x; 1.0083x over previous
#include <cuda_runtime.h>
#include <math.h>
#include <stdint.h>

#define Bdim 8
#define Vn   256
#define Hn   128
#define NR   2048      /* B*V   */
#define NE   524288    /* B*V*V */

// ---------------- device scratch (no allocation allowed) ----------------
__device__ float g_Uh[NR * Hn];
__device__ float g_Vh[NR * Hn];
__device__ float g_Ah[NR * Hn];
__device__ float g_Bh[NR * Hn];
__device__ float g_hnew[NR * Hn];
__device__ float g_esum[Hn];
__device__ float g_esq[Hn];
__device__ float g_escale[Hn];
__device__ float g_eshift[Hn];
__device__ float g_enew[(size_t)NE * Hn];   // 268 MB spill of e_new

// ---------------- helpers ----------------
__device__ __forceinline__ unsigned smem_u32(const void* p) {
    unsigned a;
    asm("{ .reg .u64 t; cvta.to.shared.u64 t, %1; cvt.u32.u64 %0, t; }"
        : "=r"(a) : "l"(p));
    return a;
}
__device__ __forceinline__ void cp_async16(unsigned dst, const void* src) {
    asm volatile("cp.async.cg.shared.global [%0], [%1], 16;\n" :: "r"(dst), "l"(src));
}
__device__ __forceinline__ uint32_t f2tf32(float f) {
    uint32_t u;
    asm("cvt.rna.tf32.f32 %0, %1;" : "=r"(u) : "f"(f));
    return u;
}
__device__ __forceinline__ float fast_sigmoid(float x) {
    float t;
    asm("tanh.approx.f32 %0, %1;" : "=f"(t) : "f"(0.5f * x));
    return 0.5f * t + 0.5f;
}

// ---------------- kernels ----------------

// two h-linears per launch; launch with which==0 also zeroes BN accumulators
#define HL_STR 132
__global__ __launch_bounds__(256)
void k_hlin2(const float* __restrict__ h,
             const float* __restrict__ W1, const float* __restrict__ b1,
             const float* __restrict__ W2, const float* __restrict__ b2,
             int which) {
    __shared__ float hs[16 * HL_STR];
    __shared__ float Ws[128 * HL_STR];
    const int t = threadIdx.x;
    const int lane = t & 31, wq = t >> 5;
    const int rbase = blockIdx.x * 16;
    if (which == 0 && blockIdx.x == 0 && t < Hn) { g_esum[t] = 0.f; g_esq[t] = 0.f; }
    {
        int idx0 = t, idx1 = t + 256;
        int r0 = idx0 >> 5, kq0 = idx0 & 31;
        int r1 = idx1 >> 5, kq1 = idx1 & 31;
        *(float4*)(hs + r0 * HL_STR + kq0 * 4) = *(const float4*)(h + (size_t)(rbase + r0) * Hn + kq0 * 4);
        *(float4*)(hs + r1 * HL_STR + kq1 * 4) = *(const float4*)(h + (size_t)(rbase + r1) * Hn + kq1 * 4);
    }
    const float* Wp[2]; const float* bp[2]; float* Op[2];
    Wp[0] = W1; Wp[1] = W2; bp[0] = b1; bp[1] = b2;
    if (which) { Op[0] = g_Ah; Op[1] = g_Bh; } else { Op[0] = g_Uh; Op[1] = g_Vh; }
    const int r0 = wq * 2, r1 = wq * 2 + 1;
    for (int a = 0; a < 2; a++) {
        __syncthreads();
        const float* W = Wp[a];
#pragma unroll
        for (int i = 0; i < 16; i++) {
            int idx = t + i * 256;
            int o = idx >> 5, kq = idx & 31;
            *(float4*)(Ws + o * HL_STR + kq * 4) = *(const float4*)(W + (size_t)o * Hn + kq * 4);
        }
        __syncthreads();
        float acc0[4] = {0.f, 0.f, 0.f, 0.f};
        float acc1[4] = {0.f, 0.f, 0.f, 0.f};
#pragma unroll 4
        for (int k4 = 0; k4 < 32; k4++) {
            float4 h0 = *(const float4*)(hs + r0 * HL_STR + k4 * 4);
            float4 h1 = *(const float4*)(hs + r1 * HL_STR + k4 * 4);
#pragma unroll
            for (int c = 0; c < 4; c++) {
                float4 w = *(const float4*)(Ws + (lane + 32 * c) * HL_STR + k4 * 4);
                acc0[c] += h0.x * w.x + h0.y * w.y + h0.z * w.z + h0.w * w.w;
                acc1[c] += h1.x * w.x + h1.y * w.y + h1.z * w.z + h1.w * w.w;
            }
        }
        float* O = Op[a];
        const float* bb = bp[a];
#pragma unroll
        for (int c = 0; c < 4; c++) {
            int col = lane + 32 * c;
            float bv = bb[col];
            O[(size_t)(rbase + r0) * Hn + col] = acc0[c] + bv;
            O[(size_t)(rbase + r1) * Hn + col] = acc1[c] + bv;
        }
    }
}

// Pass 1: tf32 mma.sync GEMM + coalesced fused epilogue, 2 CTAs/SM,
// 2 independent 4-warp groups per CTA (named barriers), 32-row chunks.
// W stored PAIRED: Wp2[(ks*4+tig)*132 + n] = (W[8ks+tig][n], W[8ks+tig+4][n])
// so each B-fragment is one LDS.64 (bank-conflict-free at stride 132).
#define AS_STRIDE 132
#define WP_FLOATS 16896               /* 64*132 float2 */
#define BUF_FLOATS 4224               /* 32*132 */
#define GS_OFF    25344               /* 16896 + 2*4224 */
#define SMEM_FLOATS 25600             /* 102400 B -> 2 CTAs/SM */
// reduction scratch inside retired Wp area (floats): 8 warps x 132
#define RED_SQ    1056
#define RED_AGG   2112

__global__ __launch_bounds__(256, 2)
void k_pass1(const float* __restrict__ e,
             const int* __restrict__ graph,
             const float* __restrict__ Cw,
             const float* __restrict__ Cb) {
    extern __shared__ float sm[];
    uint32_t* WpU = (uint32_t*)sm;
    int* gs = (int*)(sm + GS_OFF);

    const int p = blockIdx.x, b = p >> 8;
    const int t = threadIdx.x;
    const int lane = t & 31, wid = t >> 5;
    const int g  = wid >> 2;              // group 0/1
    const int wq = wid & 3;               // warp-in-group = h block
    const int gid = lane >> 2, tig = lane & 3;
    const int barid = g + 1;

    float* As = sm + WP_FLOATS + g * BUF_FLOATS;   // group-private 32-row buffer
    const unsigned dbase = smem_u32(As);
    const float* ebase = e + (size_t)p * Vn * Hn;
    const int gt = t & 127;

    // issue first chunk for own group (chunk rows j0 = g*32)
    {
        int j0 = g * 32;
#pragma unroll
        for (int i = 0; i < 8; i++) {
            int fid = i * 128 + gt;
            int row = fid >> 5, kq = fid & 31;
            cp_async16(dbase + (row * AS_STRIDE + kq * 4) * 4,
                       ebase + (size_t)(j0 + row) * Hn + kq * 4);
        }
        asm volatile("cp.async.commit_group;\n");
    }

    // stage paired W (coalesced LDG over Cw[n][k])
    for (int i = t; i < Hn * Hn; i += 256) {
        int n = i >> 7, k = i & 127;
        WpU[(((k >> 3) * 4 + (k & 3)) * AS_STRIDE + n) * 2 + ((k >> 2) & 1)] = f2tf32(Cw[i]);
    }
    gs[t] = graph[p * Vn + t];

    const int h4 = lane * 4;
    float4 bias4;
    {
        float4 bb = *(const float4*)(g_Bh + (size_t)p * Hn + h4);
        float4 cb = *(const float4*)(Cb + h4);
        bias4 = make_float4(bb.x + cb.x, bb.y + cb.y, bb.z + cb.z, bb.w + cb.w);
    }
    float4 sum4 = make_float4(0.f, 0.f, 0.f, 0.f);
    float4 sq4  = make_float4(0.f, 0.f, 0.f, 0.f);
    float4 agg4 = make_float4(0.f, 0.f, 0.f, 0.f);

    __syncthreads();    // W + gs visible everywhere

    const uint32_t* AbufU = (const uint32_t*)As;
    const uint2* Wp2 = (const uint2*)sm;
    const float* AhB = g_Ah + (size_t)b * Vn * Hn;
    const float* VhB = g_Vh + (size_t)b * Vn * Hn;

    for (int c = 0; c < 4; c++) {
        const int j0 = (c * 2 + g) * 32;
        asm volatile("cp.async.wait_group 0;\n" ::: "memory");
        asm volatile("bar.sync %0, 128;" :: "r"(barid) : "memory");

        // ---- GEMM: warp tile 32(j) x 32(h) over the 32-row chunk ----
        float cf[2][4][4];
#pragma unroll
        for (int rg = 0; rg < 2; rg++)
#pragma unroll
            for (int nt = 0; nt < 4; nt++)
#pragma unroll
                for (int q = 0; q < 4; q++) cf[rg][nt][q] = 0.f;

#pragma unroll 2
        for (int ks = 0; ks < 16; ks++) {
            int k0 = ks * 8 + tig;
            uint32_t a[2][4];
#pragma unroll
            for (int rg = 0; rg < 2; rg++) {
                int r = rg * 16 + gid;
                a[rg][0] = AbufU[r * AS_STRIDE + k0];
                a[rg][1] = AbufU[(r + 8) * AS_STRIDE + k0];
                a[rg][2] = AbufU[r * AS_STRIDE + k0 + 4];
                a[rg][3] = AbufU[(r + 8) * AS_STRIDE + k0 + 4];
            }
            uint2 bfr[4];
#pragma unroll
            for (int nt = 0; nt < 4; nt++)
                bfr[nt] = Wp2[(ks * 4 + tig) * AS_STRIDE + wq * 32 + nt * 8 + gid];
#pragma unroll
            for (int rg = 0; rg < 2; rg++)
#pragma unroll
                for (int nt = 0; nt < 4; nt++) {
                    asm volatile(
                        "mma.sync.aligned.m16n8k8.row.col.f32.tf32.tf32.f32 "
                        "{%0,%1,%2,%3},{%4,%5,%6,%7},{%8,%9},{%0,%1,%2,%3};"
                        : "+f"(cf[rg][nt][0]), "+f"(cf[rg][nt][1]),
                          "+f"(cf[rg][nt][2]), "+f"(cf[rg][nt][3])
                        : "r"(a[rg][0]), "r"(a[rg][1]), "r"(a[rg][2]), "r"(a[rg][3]),
                          "r"(bfr[nt].x), "r"(bfr[nt].y));
                }
        }

        asm volatile("bar.sync %0, 128;" :: "r"(barid) : "memory");
        // ---- transpose fragments into the dead chunk buffer ----
#pragma unroll
        for (int rg = 0; rg < 2; rg++)
#pragma unroll
            for (int half = 0; half < 2; half++) {
                int jl = rg * 16 + half * 8 + gid;
#pragma unroll
                for (int nt = 0; nt < 4; nt++) {
                    int h = wq * 32 + nt * 8 + tig * 2;
                    *(float2*)(As + jl * AS_STRIDE + h) =
                        make_float2(cf[rg][nt][half * 2], cf[rg][nt][half * 2 + 1]);
                }
            }
        asm volatile("bar.sync %0, 128;" :: "r"(barid) : "memory");

        // ---- coalesced epilogue: warp owns rows [wq*8, wq*8+8) of chunk ----
#pragma unroll
        for (int r = 0; r < 8; r++) {
            int jl = wq * 8 + r;
            int j  = j0 + jl;
            float4 cv = *(const float4*)(As + jl * AS_STRIDE + h4);
            float4 ah = *(const float4*)(AhB + (size_t)j * Hn + h4);
            float4 en;
            en.x = cv.x + ah.x + bias4.x;
            en.y = cv.y + ah.y + bias4.y;
            en.z = cv.z + ah.z + bias4.z;
            en.w = cv.w + ah.w + bias4.w;
            *(float4*)(g_enew + ((size_t)p * Vn + j) * Hn + h4) = en;
            sum4.x += en.x; sum4.y += en.y; sum4.z += en.z; sum4.w += en.w;
            sq4.x += en.x * en.x; sq4.y += en.y * en.y;
            sq4.z += en.z * en.z; sq4.w += en.w * en.w;
            if (!gs[j]) {
                float4 vh = *(const float4*)(VhB + (size_t)j * Hn + h4);
                agg4.x += fast_sigmoid(en.x) * vh.x;
                agg4.y += fast_sigmoid(en.y) * vh.y;
                agg4.z += fast_sigmoid(en.z) * vh.z;
                agg4.w += fast_sigmoid(en.w) * vh.w;
            }
        }
        asm volatile("bar.sync %0, 128;" :: "r"(barid) : "memory");

        if (c < 3) {
            int jn = ((c + 1) * 2 + g) * 32;
#pragma unroll
            for (int i = 0; i < 8; i++) {
                int fid = i * 128 + gt;
                int row = fid >> 5, kq = fid & 31;
                cp_async16(dbase + (row * AS_STRIDE + kq * 4) * 4,
                           ebase + (size_t)(jn + row) * Hn + kq * 4);
            }
            asm volatile("cp.async.commit_group;\n");
        }
    }

    // ---- block reduction via retired Wp area ----
    float* redS = sm;
    __syncthreads();
    *(float4*)(redS + wid * AS_STRIDE + h4)           = sum4;
    *(float4*)(redS + RED_SQ + wid * AS_STRIDE + h4)  = sq4;
    *(float4*)(redS + RED_AGG + wid * AS_STRIDE + h4) = agg4;
    __syncthreads();
    if (t < Hn) {
        float s = 0.f, q = 0.f, gg = 0.f;
#pragma unroll
        for (int w = 0; w < 8; w++) {
            s  += redS[w * AS_STRIDE + t];
            q  += redS[RED_SQ + w * AS_STRIDE + t];
            gg += redS[RED_AGG + w * AS_STRIDE + t];
        }
        atomicAdd(&g_esum[t], s);
        atomicAdd(&g_esq[t],  q);
        g_hnew[(size_t)p * Hn + t] = g_Uh[(size_t)p * Hn + t] + gg;
    }
}

__global__ void k_estats(const float* __restrict__ gam,
                         const float* __restrict__ bet) {
    int t = threadIdx.x;
    if (t < Hn) {
        float mean = g_esum[t] * (1.0f / NE);
        float var  = g_esq[t] * (1.0f / NE) - mean * mean;
        float scale = gam[t] * rsqrtf(var + 1e-5f);
        g_escale[t] = scale;
        g_eshift[t] = bet[t] - mean * scale;
    }
}

// pass 2 over e: normalize + relu + residual (blocks < 65536), plus the
// h-side batchnorm as tail blocks (65536..65663) running concurrently.
__global__ void k_epass2(const float* __restrict__ ein,
                         float* __restrict__ eout,
                         const float* __restrict__ hin,
                         const float* __restrict__ gamh,
                         const float* __restrict__ beth,
                         float* __restrict__ hout) {
    if (blockIdx.x < 65536) {
        size_t idx = (size_t)blockIdx.x * blockDim.x + threadIdx.x;  // float4 idx
        int h0 = (int)((idx * 4) & 127);
        float4 x = ((const float4*)g_enew)[idx];
        float4 a = ((const float4*)ein)[idx];
        float4 o;
        o.x = a.x + fmaxf(x.x * g_escale[h0]     + g_eshift[h0],     0.f);
        o.y = a.y + fmaxf(x.y * g_escale[h0 + 1] + g_eshift[h0 + 1], 0.f);
        o.z = a.z + fmaxf(x.z * g_escale[h0 + 2] + g_eshift[h0 + 2], 0.f);
        o.w = a.w + fmaxf(x.w * g_escale[h0 + 3] + g_eshift[h0 + 3], 0.f);
        ((float4*)eout)[idx] = o;
    } else {
        int h = blockIdx.x - 65536, t = threadIdx.x;
        float v[8];
        float s = 0.f, q = 0.f;
#pragma unroll
        for (int r = 0; r < 8; r++) {
            float x = g_hnew[(size_t)(t * 8 + r) * Hn + h];
            v[r] = x; s += x; q += x * x;
        }
        __shared__ float rs[256], rq[256];
        rs[t] = s; rq[t] = q; __syncthreads();
        for (int o = 128; o > 0; o >>= 1) {
            if (t < o) { rs[t] += rs[t + o]; rq[t] += rq[t + o]; }
            __syncthreads();
        }
        __shared__ float sc, sh;
        if (t == 0) {
            float mean = rs[0] * (1.0f / NR);
            float var  = rq[0] * (1.0f / NR) - mean * mean;
            float scale = gamh[h] * rsqrtf(var + 1e-5f);
            sc = scale; sh = beth[h] - mean * scale;
        }
        __syncthreads();
#pragma unroll
        for (int r = 0; r < 8; r++) {
            int row = t * 8 + r;
            float y = fmaxf(v[r] * sc + sh, 0.f);
            hout[(size_t)row * Hn + h] = hin[(size_t)row * Hn + h] + y;
        }
    }
}

// ---------------- launch ----------------
extern "C" void kernel_launch(void* const* d_in, const int* in_sizes, int n_in,
                              void* d_out, int out_size) {
    const float* h   = (const float*)d_in[0];
    const float* e   = (const float*)d_in[1];
    const int*   gra = (const int*)  d_in[2];
    const float* Uw  = (const float*)d_in[3],  *Ub = (const float*)d_in[4];
    const float* Vw  = (const float*)d_in[5],  *Vb = (const float*)d_in[6];
    const float* Aw  = (const float*)d_in[7],  *Ab = (const float*)d_in[8];
    const float* Bw  = (const float*)d_in[9],  *Bb = (const float*)d_in[10];
    const float* Cw  = (const float*)d_in[11], *Cb = (const float*)d_in[12];
    const float* gh  = (const float*)d_in[13], *bh = (const float*)d_in[14];
    const float* ge  = (const float*)d_in[15], *be = (const float*)d_in[16];

    float* out  = (float*)d_out;
    float* hout = out;                        // [2048,128]
    float* eout = out + (size_t)NR * Hn;      // [8,256,256,128]

    const int smemE = SMEM_FLOATS * 4;        // 102400 B -> 2 CTAs/SM
    cudaFuncSetAttribute(k_pass1, cudaFuncAttributeMaxDynamicSharedMemorySize, smemE);

    k_hlin2 <<<128, 256>>>(h, Uw, Ub, Vw, Vb, 0);   // also zeroes BN accumulators
    k_hlin2 <<<128, 256>>>(h, Aw, Ab, Bw, Bb, 1);
    k_pass1 <<<NR, 256, smemE>>>(e, gra, Cw, Cb);
    k_estats<<<1, 128>>>(ge, be);
    k_epass2<<<65664, 256>>>(e, eout, h, gh, bh, hout);
}

// round 11
// speedup vs baseline: 1.4494x; 1.0976x over previous
#include <cuda_runtime.h>
#include <cuda_fp16.h>
#include <math.h>
#include <stdint.h>

#define Bdim 8
#define Vn   256
#define Hn   128
#define NR   2048      /* B*V   */
#define NE   524288    /* B*V*V */

// ---------------- device scratch (no allocation allowed) ----------------
__device__ float g_Uh[NR * Hn];
__device__ float g_Vh[NR * Hn];
__device__ float g_Ah[NR * Hn];
__device__ float g_Bh[NR * Hn];
__device__ float g_hnew[NR * Hn];
__device__ float g_esum[Hn];
__device__ float g_esq[Hn];
__device__ __half g_enew[(size_t)NE * Hn];   // 134 MB fp16 spill of e_new

// ---------------- helpers ----------------
__device__ __forceinline__ unsigned smem_u32(const void* p) {
    unsigned a;
    asm("{ .reg .u64 t; cvta.to.shared.u64 t, %1; cvt.u32.u64 %0, t; }"
        : "=r"(a) : "l"(p));
    return a;
}
__device__ __forceinline__ void cp_async16(unsigned dst, const void* src) {
    asm volatile("cp.async.cg.shared.global [%0], [%1], 16;\n" :: "r"(dst), "l"(src));
}
__device__ __forceinline__ uint32_t f2tf32(float f) {
    uint32_t u;
    asm("cvt.rna.tf32.f32 %0, %1;" : "=r"(u) : "f"(f));
    return u;
}
__device__ __forceinline__ float fast_sigmoid(float x) {
    float t;
    asm("tanh.approx.f32 %0, %1;" : "=f"(t) : "f"(0.5f * x));
    return 0.5f * t + 0.5f;
}

// ---------------- kernels ----------------

// two h-linears per launch; launch with which==0 also zeroes BN accumulators
#define HL_STR 132
__global__ __launch_bounds__(256)
void k_hlin2(const float* __restrict__ h,
             const float* __restrict__ W1, const float* __restrict__ b1,
             const float* __restrict__ W2, const float* __restrict__ b2,
             int which) {
    __shared__ float hs[16 * HL_STR];
    __shared__ float Ws[128 * HL_STR];
    const int t = threadIdx.x;
    const int lane = t & 31, wq = t >> 5;
    const int rbase = blockIdx.x * 16;
    if (which == 0 && blockIdx.x == 0 && t < Hn) { g_esum[t] = 0.f; g_esq[t] = 0.f; }
    {
        int idx0 = t, idx1 = t + 256;
        int r0 = idx0 >> 5, kq0 = idx0 & 31;
        int r1 = idx1 >> 5, kq1 = idx1 & 31;
        *(float4*)(hs + r0 * HL_STR + kq0 * 4) = *(const float4*)(h + (size_t)(rbase + r0) * Hn + kq0 * 4);
        *(float4*)(hs + r1 * HL_STR + kq1 * 4) = *(const float4*)(h + (size_t)(rbase + r1) * Hn + kq1 * 4);
    }
    const float* Wp[2]; const float* bp[2]; float* Op[2];
    Wp[0] = W1; Wp[1] = W2; bp[0] = b1; bp[1] = b2;
    if (which) { Op[0] = g_Ah; Op[1] = g_Bh; } else { Op[0] = g_Uh; Op[1] = g_Vh; }
    const int r0 = wq * 2, r1 = wq * 2 + 1;
    for (int a = 0; a < 2; a++) {
        __syncthreads();
        const float* W = Wp[a];
#pragma unroll
        for (int i = 0; i < 16; i++) {
            int idx = t + i * 256;
            int o = idx >> 5, kq = idx & 31;
            *(float4*)(Ws + o * HL_STR + kq * 4) = *(const float4*)(W + (size_t)o * Hn + kq * 4);
        }
        __syncthreads();
        float acc0[4] = {0.f, 0.f, 0.f, 0.f};
        float acc1[4] = {0.f, 0.f, 0.f, 0.f};
#pragma unroll 4
        for (int k4 = 0; k4 < 32; k4++) {
            float4 h0 = *(const float4*)(hs + r0 * HL_STR + k4 * 4);
            float4 h1 = *(const float4*)(hs + r1 * HL_STR + k4 * 4);
#pragma unroll
            for (int c = 0; c < 4; c++) {
                float4 w = *(const float4*)(Ws + (lane + 32 * c) * HL_STR + k4 * 4);
                acc0[c] += h0.x * w.x + h0.y * w.y + h0.z * w.z + h0.w * w.w;
                acc1[c] += h1.x * w.x + h1.y * w.y + h1.z * w.z + h1.w * w.w;
            }
        }
        float* O = Op[a];
        const float* bb = bp[a];
#pragma unroll
        for (int c = 0; c < 4; c++) {
            int col = lane + 32 * c;
            float bv = bb[col];
            O[(size_t)(rbase + r0) * Hn + col] = acc0[c] + bv;
            O[(size_t)(rbase + r1) * Hn + col] = acc1[c] + bv;
        }
    }
}

// Pass 1: tf32 mma.sync GEMM + coalesced fused epilogue, 2 CTAs/SM,
// 2 independent 4-warp groups per CTA (named barriers), 32-row chunks.
// W stored PAIRED (float2 of k,k+4) so each B-fragment is one LDS.64.
// e_new spilled as fp16 (half2 pairs), stats kept fp32.
#define AS_STRIDE 132
#define WP_FLOATS 16896               /* 64*132 float2 */
#define BUF_FLOATS 4224               /* 32*132 */
#define GS_OFF    25344               /* 16896 + 2*4224 */
#define SMEM_FLOATS 25600             /* 102400 B -> 2 CTAs/SM */
// reduction scratch inside retired Wp area (floats): 8 warps x 132
#define RED_SQ    1056
#define RED_AGG   2112

__global__ __launch_bounds__(256, 2)
void k_pass1(const float* __restrict__ e,
             const int* __restrict__ graph,
             const float* __restrict__ Cw,
             const float* __restrict__ Cb) {
    extern __shared__ float sm[];
    uint32_t* WpU = (uint32_t*)sm;
    int* gs = (int*)(sm + GS_OFF);

    const int p = blockIdx.x, b = p >> 8;
    const int t = threadIdx.x;
    const int lane = t & 31, wid = t >> 5;
    const int g  = wid >> 2;              // group 0/1
    const int wq = wid & 3;               // warp-in-group = h block
    const int gid = lane >> 2, tig = lane & 3;
    const int barid = g + 1;

    float* As = sm + WP_FLOATS + g * BUF_FLOATS;   // group-private 32-row buffer
    const unsigned dbase = smem_u32(As);
    const float* ebase = e + (size_t)p * Vn * Hn;
    const int gt = t & 127;

    // issue first chunk for own group (chunk rows j0 = g*32)
    {
        int j0 = g * 32;
#pragma unroll
        for (int i = 0; i < 8; i++) {
            int fid = i * 128 + gt;
            int row = fid >> 5, kq = fid & 31;
            cp_async16(dbase + (row * AS_STRIDE + kq * 4) * 4,
                       ebase + (size_t)(j0 + row) * Hn + kq * 4);
        }
        asm volatile("cp.async.commit_group;\n");
    }

    // stage paired W (coalesced LDG over Cw[n][k])
    for (int i = t; i < Hn * Hn; i += 256) {
        int n = i >> 7, k = i & 127;
        WpU[(((k >> 3) * 4 + (k & 3)) * AS_STRIDE + n) * 2 + ((k >> 2) & 1)] = f2tf32(Cw[i]);
    }
    gs[t] = graph[p * Vn + t];

    const int h4 = lane * 4;
    float4 bias4;
    {
        float4 bb = *(const float4*)(g_Bh + (size_t)p * Hn + h4);
        float4 cb = *(const float4*)(Cb + h4);
        bias4 = make_float4(bb.x + cb.x, bb.y + cb.y, bb.z + cb.z, bb.w + cb.w);
    }
    float4 sum4 = make_float4(0.f, 0.f, 0.f, 0.f);
    float4 sq4  = make_float4(0.f, 0.f, 0.f, 0.f);
    float4 agg4 = make_float4(0.f, 0.f, 0.f, 0.f);

    __syncthreads();    // W + gs visible everywhere

    const uint32_t* AbufU = (const uint32_t*)As;
    const uint2* Wp2 = (const uint2*)sm;
    const float* AhB = g_Ah + (size_t)b * Vn * Hn;
    const float* VhB = g_Vh + (size_t)b * Vn * Hn;

    for (int c = 0; c < 4; c++) {
        const int j0 = (c * 2 + g) * 32;
        asm volatile("cp.async.wait_group 0;\n" ::: "memory");
        asm volatile("bar.sync %0, 128;" :: "r"(barid) : "memory");

        // ---- GEMM: warp tile 32(j) x 32(h) over the 32-row chunk ----
        float cf[2][4][4];
#pragma unroll
        for (int rg = 0; rg < 2; rg++)
#pragma unroll
            for (int nt = 0; nt < 4; nt++)
#pragma unroll
                for (int q = 0; q < 4; q++) cf[rg][nt][q] = 0.f;

#pragma unroll 2
        for (int ks = 0; ks < 16; ks++) {
            int k0 = ks * 8 + tig;
            uint32_t a[2][4];
#pragma unroll
            for (int rg = 0; rg < 2; rg++) {
                int r = rg * 16 + gid;
                a[rg][0] = AbufU[r * AS_STRIDE + k0];
                a[rg][1] = AbufU[(r + 8) * AS_STRIDE + k0];
                a[rg][2] = AbufU[r * AS_STRIDE + k0 + 4];
                a[rg][3] = AbufU[(r + 8) * AS_STRIDE + k0 + 4];
            }
            uint2 bfr[4];
#pragma unroll
            for (int nt = 0; nt < 4; nt++)
                bfr[nt] = Wp2[(ks * 4 + tig) * AS_STRIDE + wq * 32 + nt * 8 + gid];
#pragma unroll
            for (int rg = 0; rg < 2; rg++)
#pragma unroll
                for (int nt = 0; nt < 4; nt++) {
                    asm volatile(
                        "mma.sync.aligned.m16n8k8.row.col.f32.tf32.tf32.f32 "
                        "{%0,%1,%2,%3},{%4,%5,%6,%7},{%8,%9},{%0,%1,%2,%3};"
                        : "+f"(cf[rg][nt][0]), "+f"(cf[rg][nt][1]),
                          "+f"(cf[rg][nt][2]), "+f"(cf[rg][nt][3])
                        : "r"(a[rg][0]), "r"(a[rg][1]), "r"(a[rg][2]), "r"(a[rg][3]),
                          "r"(bfr[nt].x), "r"(bfr[nt].y));
                }
        }

        asm volatile("bar.sync %0, 128;" :: "r"(barid) : "memory");
        // ---- transpose fragments into the dead chunk buffer ----
#pragma unroll
        for (int rg = 0; rg < 2; rg++)
#pragma unroll
            for (int half = 0; half < 2; half++) {
                int jl = rg * 16 + half * 8 + gid;
#pragma unroll
                for (int nt = 0; nt < 4; nt++) {
                    int h = wq * 32 + nt * 8 + tig * 2;
                    *(float2*)(As + jl * AS_STRIDE + h) =
                        make_float2(cf[rg][nt][half * 2], cf[rg][nt][half * 2 + 1]);
                }
            }
        asm volatile("bar.sync %0, 128;" :: "r"(barid) : "memory");

        // ---- coalesced epilogue: warp owns rows [wq*8, wq*8+8) of chunk ----
#pragma unroll
        for (int r = 0; r < 8; r++) {
            int jl = wq * 8 + r;
            int j  = j0 + jl;
            float4 cv = *(const float4*)(As + jl * AS_STRIDE + h4);
            float4 ah = *(const float4*)(AhB + (size_t)j * Hn + h4);
            float4 en;
            en.x = cv.x + ah.x + bias4.x;
            en.y = cv.y + ah.y + bias4.y;
            en.z = cv.z + ah.z + bias4.z;
            en.w = cv.w + ah.w + bias4.w;
            // fp16 spill (streaming store, 8B/thread coalesced)
            {
                __half2 ha = __floats2half2_rn(en.x, en.y);
                __half2 hb = __floats2half2_rn(en.z, en.w);
                uint2 pk;
                pk.x = *(uint32_t*)&ha;
                pk.y = *(uint32_t*)&hb;
                __stcs((uint2*)(g_enew + ((size_t)p * Vn + j) * Hn) + lane, pk);
            }
            sum4.x += en.x; sum4.y += en.y; sum4.z += en.z; sum4.w += en.w;
            sq4.x += en.x * en.x; sq4.y += en.y * en.y;
            sq4.z += en.z * en.z; sq4.w += en.w * en.w;
            if (!gs[j]) {
                float4 vh = *(const float4*)(VhB + (size_t)j * Hn + h4);
                agg4.x += fast_sigmoid(en.x) * vh.x;
                agg4.y += fast_sigmoid(en.y) * vh.y;
                agg4.z += fast_sigmoid(en.z) * vh.z;
                agg4.w += fast_sigmoid(en.w) * vh.w;
            }
        }
        asm volatile("bar.sync %0, 128;" :: "r"(barid) : "memory");

        if (c < 3) {
            int jn = ((c + 1) * 2 + g) * 32;
#pragma unroll
            for (int i = 0; i < 8; i++) {
                int fid = i * 128 + gt;
                int row = fid >> 5, kq = fid & 31;
                cp_async16(dbase + (row * AS_STRIDE + kq * 4) * 4,
                           ebase + (size_t)(jn + row) * Hn + kq * 4);
            }
            asm volatile("cp.async.commit_group;\n");
        }
    }

    // ---- block reduction via retired Wp area ----
    float* redS = sm;
    __syncthreads();
    *(float4*)(redS + wid * AS_STRIDE + h4)           = sum4;
    *(float4*)(redS + RED_SQ + wid * AS_STRIDE + h4)  = sq4;
    *(float4*)(redS + RED_AGG + wid * AS_STRIDE + h4) = agg4;
    __syncthreads();
    if (t < Hn) {
        float s = 0.f, q = 0.f, gg = 0.f;
#pragma unroll
        for (int w = 0; w < 8; w++) {
            s  += redS[w * AS_STRIDE + t];
            q  += redS[RED_SQ + w * AS_STRIDE + t];
            gg += redS[RED_AGG + w * AS_STRIDE + t];
        }
        atomicAdd(&g_esum[t], s);
        atomicAdd(&g_esq[t],  q);
        g_hnew[(size_t)p * Hn + t] = g_Uh[(size_t)p * Hn + t] + gg;
    }
}

// pass 2 over e: normalize + relu + residual (blocks < 65536), h-side
// batchnorm as tail blocks. BN scale/shift derived in-block from g_esum/g_esq.
__global__ void k_epass2(const float* __restrict__ ein,
                         float* __restrict__ eout,
                         const float* __restrict__ game,
                         const float* __restrict__ bete,
                         const float* __restrict__ hin,
                         const float* __restrict__ gamh,
                         const float* __restrict__ beth,
                         float* __restrict__ hout) {
    if (blockIdx.x < 65536) {
        __shared__ float scS[128], shS[128];
        int t = threadIdx.x;
        if (t < 128) {
            float mean = g_esum[t] * (1.0f / NE);
            float var  = g_esq[t] * (1.0f / NE) - mean * mean;
            float sc = game[t] * rsqrtf(var + 1e-5f);
            scS[t] = sc;
            shS[t] = bete[t] - mean * sc;
        }
        __syncthreads();
        size_t idx = (size_t)blockIdx.x * blockDim.x + t;   // 4-channel unit idx
        int h0 = (int)((idx * 4) & 127);
        uint2 pk = __ldcs((const uint2*)g_enew + idx);
        __half2 ha = *(__half2*)&pk.x;
        __half2 hb = *(__half2*)&pk.y;
        float2 f01 = __half22float2(ha);
        float2 f23 = __half22float2(hb);
        float4 a = __ldcs((const float4*)ein + idx);
        float4 o;
        o.x = a.x + fmaxf(f01.x * scS[h0]     + shS[h0],     0.f);
        o.y = a.y + fmaxf(f01.y * scS[h0 + 1] + shS[h0 + 1], 0.f);
        o.z = a.z + fmaxf(f23.x * scS[h0 + 2] + shS[h0 + 2], 0.f);
        o.w = a.w + fmaxf(f23.y * scS[h0 + 3] + shS[h0 + 3], 0.f);
        ((float4*)eout)[idx] = o;
    } else {
        int h = blockIdx.x - 65536, t = threadIdx.x;
        float v[8];
        float s = 0.f, q = 0.f;
#pragma unroll
        for (int r = 0; r < 8; r++) {
            float x = g_hnew[(size_t)(t * 8 + r) * Hn + h];
            v[r] = x; s += x; q += x * x;
        }
        __shared__ float rs[256], rq[256];
        rs[t] = s; rq[t] = q; __syncthreads();
        for (int o = 128; o > 0; o >>= 1) {
            if (t < o) { rs[t] += rs[t + o]; rq[t] += rq[t + o]; }
            __syncthreads();
        }
        __shared__ float sc, sh;
        if (t == 0) {
            float mean = rs[0] * (1.0f / NR);
            float var  = rq[0] * (1.0f / NR) - mean * mean;
            float scale = gamh[h] * rsqrtf(var + 1e-5f);
            sc = scale; sh = beth[h] - mean * scale;
        }
        __syncthreads();
#pragma unroll
        for (int r = 0; r < 8; r++) {
            int row = t * 8 + r;
            float y = fmaxf(v[r] * sc + sh, 0.f);
            hout[(size_t)row * Hn + h] = hin[(size_t)row * Hn + h] + y;
        }
    }
}

// ---------------- launch ----------------
extern "C" void kernel_launch(void* const* d_in, const int* in_sizes, int n_in,
                              void* d_out, int out_size) {
    const float* h   = (const float*)d_in[0];
    const float* e   = (const float*)d_in[1];
    const int*   gra = (const int*)  d_in[2];
    const float* Uw  = (const float*)d_in[3],  *Ub = (const float*)d_in[4];
    const float* Vw  = (const float*)d_in[5],  *Vb = (const float*)d_in[6];
    const float* Aw  = (const float*)d_in[7],  *Ab = (const float*)d_in[8];
    const float* Bw  = (const float*)d_in[9],  *Bb = (const float*)d_in[10];
    const float* Cw  = (const float*)d_in[11], *Cb = (const float*)d_in[12];
    const float* gh  = (const float*)d_in[13], *bh = (const float*)d_in[14];
    const float* ge  = (const float*)d_in[15], *be = (const float*)d_in[16];

    float* out  = (float*)d_out;
    float* hout = out;                        // [2048,128]
    float* eout = out + (size_t)NR * Hn;      // [8,256,256,128]

    const int smemE = SMEM_FLOATS * 4;        // 102400 B -> 2 CTAs/SM
    cudaFuncSetAttribute(k_pass1, cudaFuncAttributeMaxDynamicSharedMemorySize, smemE);

    k_hlin2 <<<128, 256>>>(h, Uw, Ub, Vw, Vb, 0);   // also zeroes BN accumulators
    k_hlin2 <<<128, 256>>>(h, Aw, Ab, Bw, Bb, 1);
    k_pass1 <<<NR, 256, smemE>>>(e, gra, Cw, Cb);
    k_epass2<<<65664, 256>>>(e, eout, ge, be, h, gh, bh, hout);
}